// round 13
// baseline (speedup 1.0000x reference)
#include <cuda_runtime.h>
#include <cstdint>
#include <cstring>

#define Bx 64
#define Cx 3
#define Hx 384
#define Wx 384
#define PLANE (Hx * Wx)          // 147456
#define IMGS_PER_TEX 16
#define TEX_H (IMGS_PER_TEX * Cx * Hx)   // 18432 rows

// ---- hybrid kernel: TEX + LSU pipes interleaved per-warp via channel split ----
// Row parity alternates the channel->pipe assignment so each thread issues
// 6 TEX gathers + 6 LDG-quads over its 4 rows (50/50 pipe balance).
__global__ __launch_bounds__(256, 5) void affine_mix_kernel(
    cudaTextureObject_t t0, cudaTextureObject_t t1,
    cudaTextureObject_t t2, cudaTextureObject_t t3,
    const float* __restrict__ imgs,
    const float* __restrict__ theta,
    float* __restrict__ out)
{
    int lane  = threadIdx.x;          // 0..31
    int w     = threadIdx.y;          // 0..7
    int warpx = w & 3;
    int warpy = w >> 2;

    int x     = blockIdx.x * 128 + warpx * 32 + lane;
    int ybase = blockIdx.y * 8 + warpy * 4;
    int b     = blockIdx.z;

    const float* th = theta + b * 6;
    float t00 = __ldg(th + 0), t01 = __ldg(th + 1), t02 = __ldg(th + 2);
    float t10 = __ldg(th + 3), t11 = __ldg(th + 4), t12 = __ldg(th + 5);

    cudaTextureObject_t tex = (b & 32) ? ((b & 16) ? t3 : t2)
                                       : ((b & 16) ? t1 : t0);
    float rowb = (float)((b & (IMGS_PER_TEX - 1)) * Cx * Hx);

    float xv  = (float)x - 191.5f;
    float ixx = fmaf(xv, t00, t02 + 191.5f);
    float iyx = fmaf(xv, t10, t12 + 191.5f);

    const float* img  = imgs + (size_t)b * (Cx * PLANE);
    float*       outb = out  + (size_t)b * (Cx * PLANE);

#pragma unroll
    for (int r = 0; r < 4; r++) {
        int y = ybase + r;
        float yv = (float)y - 191.5f;
        float ix = fmaf(yv, t01, ixx);
        float iy = fmaf(yv, t11, iyx);

        float fx0 = floorf(ix), fy0 = floorf(iy);
        float wx1 = ix - fx0,  wy1 = iy - fy0;
        float wx0 = 1.0f - wx1, wy0 = 1.0f - wy1;

        int x0 = (int)fx0, y0 = (int)fy0;
        int x1 = x0 + 1,  y1 = y0 + 1;

        // y-validity folded (exact {0,1} or weight): TEX-path weights
        float vty0 = (y0 >= 0 && y0 < Hx) ? wy0 : 0.0f;
        float vty1 = (y1 >= 0 && y1 < Hx) ? wy1 : 0.0f;
        float wt00 = wx0 * vty0, wt10 = wx1 * vty0;
        float wt01 = wx0 * vty1, wt11 = wx1 * vty1;

        // x-validity on top: LDG-path weights (exact multiplies by {0,1})
        float vx0 = (x0 >= 0 && x0 < Wx) ? 1.0f : 0.0f;
        float vx1 = (x1 >= 0 && x1 < Wx) ? 1.0f : 0.0f;
        float wv00 = wt00 * vx0, wv10 = wt10 * vx1;
        float wv01 = wt01 * vx0, wv11 = wt11 * vx1;

        int xc0 = min(max(x0, 0), Wx - 1);
        int xc1 = min(max(x1, 0), Wx - 1);
        int yc0 = min(max(y0, 0), Hx - 1);
        int yc1 = min(max(y1, 0), Hx - 1);

        int o00 = yc0 * Wx + xc0;
        int o10 = yc0 * Wx + xc1;
        int o01 = yc1 * Wx + xc0;
        int o11 = yc1 * Wx + xc1;

        float gx = fx0 + 1.0f;
        float gy = rowb + fy0 + 1.0f;

        float r0, r1, r2;

        if ((r & 1) == 0) {
            // even rows: ch0, ch1 via TEX; ch2 via LDG
            float4 g0 = tex2Dgather<float4>(tex, gx, gy, 0);
            float4 g1 = tex2Dgather<float4>(tex, gx, gy + (float)Hx, 0);
            const float* p2 = img + 2 * PLANE;
            float a2 = __ldg(p2 + o00);
            float b2 = __ldg(p2 + o10);
            float c2 = __ldg(p2 + o01);
            float d2 = __ldg(p2 + o11);

            // gather order: .w=(x0,y0) .z=(x1,y0) .x=(x0,y1) .y=(x1,y1)
            r0 = fmaf(wt00, g0.w, fmaf(wt10, g0.z, fmaf(wt01, g0.x, wt11 * g0.y)));
            r1 = fmaf(wt00, g1.w, fmaf(wt10, g1.z, fmaf(wt01, g1.x, wt11 * g1.y)));
            r2 = fmaf(wv00, a2, fmaf(wv10, b2, fmaf(wv01, c2, wv11 * d2)));
        } else {
            // odd rows: ch0 via TEX; ch1, ch2 via LDG
            float4 g0 = tex2Dgather<float4>(tex, gx, gy, 0);
            const float* p1 = img + 1 * PLANE;
            const float* p2 = img + 2 * PLANE;
            float a1 = __ldg(p1 + o00);
            float b1 = __ldg(p1 + o10);
            float c1 = __ldg(p1 + o01);
            float d1 = __ldg(p1 + o11);
            float a2 = __ldg(p2 + o00);
            float b2 = __ldg(p2 + o10);
            float c2 = __ldg(p2 + o01);
            float d2 = __ldg(p2 + o11);

            r0 = fmaf(wt00, g0.w, fmaf(wt10, g0.z, fmaf(wt01, g0.x, wt11 * g0.y)));
            r1 = fmaf(wv00, a1, fmaf(wv10, b1, fmaf(wv01, c1, wv11 * d1)));
            r2 = fmaf(wv00, a2, fmaf(wv10, b2, fmaf(wv01, c2, wv11 * d2)));
        }

        int rowoff = y * Wx + x;
        outb[0 * PLANE + rowoff] = r0;
        outb[1 * PLANE + rowoff] = r1;
        outb[2 * PLANE + rowoff] = r2;
    }
}

// ---------------- fallback: proven R3 global-gather kernel ----------------
__global__ __launch_bounds__(256) void affine_ldg_kernel(
    const float* __restrict__ imgs,
    const float* __restrict__ theta,
    float* __restrict__ out)
{
    int lane  = threadIdx.x;
    int w     = threadIdx.y;
    int warpx = w & 3;
    int warpy = w >> 2;

    int x     = blockIdx.x * 128 + warpx * 32 + lane;
    int ybase = blockIdx.y * 8 + warpy * 4;
    int b     = blockIdx.z;

    const float* th = theta + b * 6;
    float t00 = __ldg(th + 0), t01 = __ldg(th + 1), t02 = __ldg(th + 2);
    float t10 = __ldg(th + 3), t11 = __ldg(th + 4), t12 = __ldg(th + 5);

    float xv  = (float)x - 191.5f;
    float ixx = fmaf(xv, t00, t02 + 191.5f);
    float iyx = fmaf(xv, t10, t12 + 191.5f);

    const float* img  = imgs + (size_t)b * (Cx * PLANE);
    float*       outb = out  + (size_t)b * (Cx * PLANE);

#pragma unroll
    for (int r = 0; r < 4; r++) {
        int y = ybase + r;
        float yv = (float)y - 191.5f;
        float ix = fmaf(yv, t01, ixx);
        float iy = fmaf(yv, t11, iyx);

        float fx0 = floorf(ix), fy0 = floorf(iy);
        float wx1 = ix - fx0,  wy1 = iy - fy0;
        float wx0 = 1.0f - wx1, wy0 = 1.0f - wy1;

        int x0 = (int)fx0, y0 = (int)fy0;
        int x1 = x0 + 1,  y1 = y0 + 1;

        float vx0 = (x0 >= 0 && x0 < Wx) ? 1.0f : 0.0f;
        float vx1 = (x1 >= 0 && x1 < Wx) ? 1.0f : 0.0f;
        float vy0 = (y0 >= 0 && y0 < Hx) ? 1.0f : 0.0f;
        float vy1 = (y1 >= 0 && y1 < Hx) ? 1.0f : 0.0f;

        float w00 = wx0 * wy0 * vx0 * vy0;
        float w10 = wx1 * wy0 * vx1 * vy0;
        float w01 = wx0 * wy1 * vx0 * vy1;
        float w11 = wx1 * wy1 * vx1 * vy1;

        int xc0 = min(max(x0, 0), Wx - 1);
        int xc1 = min(max(x1, 0), Wx - 1);
        int yc0 = min(max(y0, 0), Hx - 1);
        int yc1 = min(max(y1, 0), Hx - 1);

        int o00 = yc0 * Wx + xc0;
        int o10 = yc0 * Wx + xc1;
        int o01 = yc1 * Wx + xc0;
        int o11 = yc1 * Wx + xc1;

        float v00c0 = __ldg(img + 0 * PLANE + o00);
        float v10c0 = __ldg(img + 0 * PLANE + o10);
        float v01c0 = __ldg(img + 0 * PLANE + o01);
        float v11c0 = __ldg(img + 0 * PLANE + o11);
        float v00c1 = __ldg(img + 1 * PLANE + o00);
        float v10c1 = __ldg(img + 1 * PLANE + o10);
        float v01c1 = __ldg(img + 1 * PLANE + o01);
        float v11c1 = __ldg(img + 1 * PLANE + o11);
        float v00c2 = __ldg(img + 2 * PLANE + o00);
        float v10c2 = __ldg(img + 2 * PLANE + o10);
        float v01c2 = __ldg(img + 2 * PLANE + o01);
        float v11c2 = __ldg(img + 2 * PLANE + o11);

        float r0 = fmaf(w00, v00c0, fmaf(w10, v10c0, fmaf(w01, v01c0, w11 * v11c0)));
        float r1 = fmaf(w00, v00c1, fmaf(w10, v10c1, fmaf(w01, v01c1, w11 * v11c1)));
        float r2 = fmaf(w00, v00c2, fmaf(w10, v10c2, fmaf(w01, v01c2, w11 * v11c2)));

        int rowoff = y * Wx + x;
        outb[0 * PLANE + rowoff] = r0;
        outb[1 * PLANE + rowoff] = r1;
        outb[2 * PLANE + rowoff] = r2;
    }
}

extern "C" void kernel_launch(void* const* d_in, const int* in_sizes, int n_in,
                              void* d_out, int out_size)
{
    const float* imgs  = (const float*)d_in[0];
    const float* theta = (const float*)d_in[1];
    float* out = (float*)d_out;

    // One-time texture-object setup OUTSIDE graph capture (proven pattern).
    static cudaTextureObject_t tex[4] = {0, 0, 0, 0};
    static const float* cached_imgs = nullptr;
    static int tex_ok = 0;

    if (cached_imgs != imgs) {
        cudaStreamCaptureStatus cs = cudaStreamCaptureStatusNone;
        cudaStreamIsCapturing(cudaStreamLegacy, &cs);
        if (cs == cudaStreamCaptureStatusNone) {
            int ok = 1;
            for (int g = 0; g < 4 && ok; g++) {
                cudaResourceDesc rd;
                memset(&rd, 0, sizeof(rd));
                rd.resType = cudaResourceTypePitch2D;
                rd.res.pitch2D.devPtr =
                    (void*)(imgs + (size_t)g * IMGS_PER_TEX * Cx * PLANE);
                rd.res.pitch2D.desc = cudaCreateChannelDesc<float>();
                rd.res.pitch2D.width = Wx;
                rd.res.pitch2D.height = TEX_H;
                rd.res.pitch2D.pitchInBytes = Wx * sizeof(float);

                cudaTextureDesc td;
                memset(&td, 0, sizeof(td));
                td.addressMode[0] = cudaAddressModeBorder;  // OOB -> 0
                td.addressMode[1] = cudaAddressModeBorder;
                td.filterMode = cudaFilterModePoint;
                td.readMode = cudaReadModeElementType;
                td.normalizedCoords = 0;

                if (cudaCreateTextureObject(&tex[g], &rd, &td, nullptr)
                    != cudaSuccess) ok = 0;
            }
            tex_ok = ok;
            cached_imgs = imgs;
        }
    }

    dim3 block(32, 8);
    dim3 grid(Wx / 128, Hx / 8, Bx);   // (3, 48, 64)
    if (tex_ok && cached_imgs == imgs) {
        affine_mix_kernel<<<grid, block>>>(tex[0], tex[1], tex[2], tex[3],
                                           imgs, theta, out);
    } else {
        affine_ldg_kernel<<<grid, block>>>(imgs, theta, out);
    }
}